// round 12
// baseline (speedup 1.0000x reference)
#include <cuda_runtime.h>
#include <cuda_bf16.h>
#include <cstdint>

#define NB 256
#define NS 2048
#define NK 64
#define LN2F 0.69314718055994531f
#define NBLK 148          // 128 chain blocks + 20 gold blocks
#define NWCH 512          // chain warps (each owns 2 segments)
#define NWGOLD 80         // gold warps

// Scratch (device globals — no allocation allowed)
__device__ float g_vecA[NB][NK];   // alpha_683 (true fwd)
__device__ float g_vecF[NB][NK];   // f = 1^T M2
__device__ float g_vecG[NB][NK];   // g = M2 1
__device__ float g_vecB[NB][NK];   // beta_1366 (true bwd)
__device__ float g_offA[NB];
__device__ float g_offG[NB];
__device__ float g_offB[NB];
__device__ float g_gold[NB];
__device__ unsigned g_done;        // zero-init; reset by last block each launch

typedef __nv_bfloat162 bf2;

__device__ __forceinline__ bf2 u2b(unsigned u) { return *reinterpret_cast<bf2*>(&u); }
__device__ __forceinline__ unsigned b2u(bf2 v) { return *reinterpret_cast<unsigned*>(&v); }

// matvec, plain-packed vector (lane i holds pair (a_2i, a_2i+1) as one bf2):
// 8x LDS.128 + 64x HFMA2; Ee/Eo = this lane's even/odd output column banks.
__device__ __forceinline__ void mv2(const bf2* __restrict__ s,
                                    const unsigned (&Ee)[32], const unsigned (&Eo)[32],
                                    float& zl, float& zh) {
    const uint4* q = (const uint4*)s;
    bf2 zz = __floats2bfloat162_rn(0.f, 0.f);
    bf2 ce0 = zz, ce1 = zz, co0 = zz, co1 = zz;
    #pragma unroll
    for (int g = 0; g < 8; g++) {
        uint4 v = q[g];
        ce0 = __hfma2(u2b(v.x), u2b(Ee[4 * g + 0]), ce0);
        co0 = __hfma2(u2b(v.x), u2b(Eo[4 * g + 0]), co0);
        ce1 = __hfma2(u2b(v.y), u2b(Ee[4 * g + 1]), ce1);
        co1 = __hfma2(u2b(v.y), u2b(Eo[4 * g + 1]), co1);
        ce0 = __hfma2(u2b(v.z), u2b(Ee[4 * g + 2]), ce0);
        co0 = __hfma2(u2b(v.z), u2b(Eo[4 * g + 2]), co0);
        ce1 = __hfma2(u2b(v.w), u2b(Ee[4 * g + 3]), ce1);
        co1 = __hfma2(u2b(v.w), u2b(Eo[4 * g + 3]), co1);
    }
    bf2 ce = __hadd2(ce0, ce1), co = __hadd2(co0, co1);
    zl = __low2float(ce) + __high2float(ce);
    zh = __low2float(co) + __high2float(co);
}

// Exact power-of-two rescale (warp max via 5 shfl), offset in log domain.
__device__ __forceinline__ void rescale(bf2& v, float& off) {
    bf2 m2 = v;
    #pragma unroll
    for (int d = 16; d; d >>= 1)
        m2 = __hmax2(m2, u2b(__shfl_xor_sync(0xffffffffu, b2u(m2), d)));
    float m = fmaxf(__low2float(m2), __high2float(m2));
    int k = (__float_as_int(m) >> 23) - 127;
    k = k < -120 ? -120 : (k > 120 ? 120 : k);
    float scl = __int_as_float((127 - k) << 23);   // 2^-k (exact in bf16)
    v = __hmul2(v, __floats2bfloat162_rn(scl, scl));
    off += (float)k * LN2F;
}

// ---- forward double-step: two independent chains X/Y interleaved, one sync ----
#define FS2(P, BX, BY) do {                                                \
    float zlX_, zhX_, zlY_, zhY_;                                          \
    mv2(mydX[P], Ee, Eo, zlX_, zhX_);                                      \
    mv2(mydY[P], Ee, Eo, zlY_, zhY_);                                      \
    float2 svX_ = BX; BX = *preX; preX += 32;                              \
    float2 svY_ = BY; BY = *preY; preY += 32;                              \
    avX = __floats2bfloat162_rn(zlX_ * __expf(svX_.x), zhX_ * __expf(svX_.y)); \
    avY = __floats2bfloat162_rn(zlY_ * __expf(svY_.x), zhY_ * __expf(svY_.y)); \
    mydX[P ^ 1][l] = avX;                                                  \
    mydY[P ^ 1][l] = avY;                                                  \
    __syncwarp();                                                          \
} while (0)

#define FS2_R(P, BX, BY) do {                                              \
    float zlX_, zhX_, zlY_, zhY_;                                          \
    mv2(mydX[P], Ee, Eo, zlX_, zhX_);                                      \
    mv2(mydY[P], Ee, Eo, zlY_, zhY_);                                      \
    float2 svX_ = BX; BX = *preX; preX += 32;                              \
    float2 svY_ = BY; BY = *preY; preY += 32;                              \
    avX = __floats2bfloat162_rn(zlX_ * __expf(svX_.x), zhX_ * __expf(svX_.y)); \
    avY = __floats2bfloat162_rn(zlY_ * __expf(svY_.x), zhY_ * __expf(svY_.y)); \
    rescale(avX, offX);                                                    \
    rescale(avY, offY);                                                    \
    mydX[P ^ 1][l] = avX;                                                  \
    mydY[P ^ 1][l] = avY;                                                  \
    __syncwarp();                                                          \
} while (0)

// ---- backward double-step ----
#define BS2(P, BX, BY) do {                                                \
    float2 svX_ = BX; BX = *preX; preX -= 32;                              \
    float2 svY_ = BY; BY = *preY; preY -= 32;                              \
    bf2 wX_ = __hmul2(avX, __floats2bfloat162_rn(__expf(svX_.x), __expf(svX_.y))); \
    bf2 wY_ = __hmul2(avY, __floats2bfloat162_rn(__expf(svY_.x), __expf(svY_.y))); \
    mydX[P][l] = wX_;                                                      \
    mydY[P][l] = wY_;                                                      \
    __syncwarp();                                                          \
    float zlX_, zhX_, zlY_, zhY_;                                          \
    mv2(mydX[P], Ee, Eo, zlX_, zhX_);                                      \
    mv2(mydY[P], Ee, Eo, zlY_, zhY_);                                      \
    avX = __floats2bfloat162_rn(zlX_, zhX_);                               \
    avY = __floats2bfloat162_rn(zlY_, zhY_);                               \
} while (0)

#define BS2_R(P, BX, BY) do {                                              \
    float2 svX_ = BX; BX = *preX; preX -= 32;                              \
    float2 svY_ = BY; BY = *preY; preY -= 32;                              \
    bf2 wX_ = __hmul2(avX, __floats2bfloat162_rn(__expf(svX_.x), __expf(svX_.y))); \
    bf2 wY_ = __hmul2(avY, __floats2bfloat162_rn(__expf(svY_.x), __expf(svY_.y))); \
    rescale(wX_, offX);                                                    \
    rescale(wY_, offY);                                                    \
    mydX[P][l] = wX_;                                                      \
    mydY[P][l] = wY_;                                                      \
    __syncwarp();                                                          \
    float zlX_, zhX_, zlY_, zhY_;                                          \
    mv2(mydX[P], Ee, Eo, zlX_, zhX_);                                      \
    mv2(mydY[P], Ee, Eo, zlY_, zhY_);                                      \
    avX = __floats2bfloat162_rn(zlX_, zhX_);                               \
    avY = __floats2bfloat162_rn(zlY_, zhY_);                               \
} while (0)

// Blocks [0,128): batch-pair p = blockIdx; 4 warps = roles {A, f, g, beta},
//   each warp runs its role for BOTH batches 2p and 2p+1 (2-chain ILP,
//   shared Er registers). 1 chain warp per SMSP.
// Blocks [128,148): gold path, 4 warps each (80 warps, 3-4 batches per warp).
// Last block to finish computes the final loss.
__global__ void __launch_bounds__(128, 1)
crf_fused(const float* __restrict__ scores, const int* __restrict__ states,
          const float* __restrict__ trans, const float* __restrict__ source,
          const float* __restrict__ sink, float* __restrict__ out)
{
    __shared__ __align__(16) bf2 vbuf[4][2][2][32];  // [warp][chain][buf][lane] 2KB
    __shared__ float red[NB];
    __shared__ int s_last;

    const int w = threadIdx.x >> 5;
    const int l = threadIdx.x & 31;

    if (blockIdx.x >= 128) {
        // ---------------- gold path ----------------
        const int gw = (blockIdx.x - 128) * 4 + w;
        for (int b = gw; b < NB; b += NWGOLD) {
            const int* st = states + b * NS;
            const float* sc = scores + (size_t)b * NS * NK;
            float acc = 0.f;
            #pragma unroll 4
            for (int t = l; t < NS; t += 32) {
                int s = st[t];
                float e = sc[t * NK + s];
                float tr = (t + 1 < NS) ? trans[s * NK + st[t + 1]] : 0.f;
                acc += e + tr;
            }
            #pragma unroll
            for (int d = 16; d; d >>= 1) acc += __shfl_xor_sync(0xffffffffu, acc, d);
            if (l == 0) g_gold[b] = acc + source[st[0]] + sink[st[NS - 1]];
        }
    } else {
        // ---------------- two segment-chains per warp ----------------
        const int b0 = 2 * blockIdx.x;       // chain X batch
        const int b1 = 2 * blockIdx.x + 1;   // chain Y batch
        const int role = w;                   // 0=A 1=f 2=g 3=beta
        const bool fwd = role < 2;
        bf2 (*mydX)[32] = vbuf[w][0];
        bf2 (*mydY)[32] = vbuf[w][1];

        // Er banks (shared by both chains): even column 2l in Ee, odd in Eo.
        unsigned Ee[32], Eo[32];
        if (fwd) {
            #pragma unroll
            for (int i2 = 0; i2 < 32; i2++) {
                const float* r0 = trans + (2 * i2) * NK;
                const float* r1 = trans + (2 * i2 + 1) * NK;
                Ee[i2] = b2u(__floats2bfloat162_rn(__expf(r0[2 * l]),     __expf(r1[2 * l])));
                Eo[i2] = b2u(__floats2bfloat162_rn(__expf(r0[2 * l + 1]), __expf(r1[2 * l + 1])));
            }
        } else {
            #pragma unroll
            for (int j2 = 0; j2 < 32; j2++) {
                float2 e0v = ((const float2*)(trans + (2 * l) * NK))[j2];
                float2 e1v = ((const float2*)(trans + (2 * l + 1) * NK))[j2];
                Ee[j2] = b2u(__floats2bfloat162_rn(__expf(e0v.x), __expf(e0v.y)));
                Eo[j2] = b2u(__floats2bfloat162_rn(__expf(e1v.x), __expf(e1v.y)));
            }
        }

        const float2* pre0X = (const float2*)(scores + (size_t)b0 * NS * NK) + l;
        const float2* pre0Y = (const float2*)(scores + (size_t)b1 * NS * NK) + l;
        float offX = 0.f, offY = 0.f;
        bf2 avX, avY;

        if (fwd) {
            int base;
            if (role == 0) {
                // alpha_0 = exp(source + scores[b,0,:])
                float2 sr = ((const float2*)source)[l];
                float2 sX = pre0X[0], sY = pre0Y[0];
                avX = __floats2bfloat162_rn(__expf(sr.x + sX.x), __expf(sr.y + sX.y));
                avY = __floats2bfloat162_rn(__expf(sr.x + sY.x), __expf(sr.y + sY.y));
                base = 1;
            } else {
                avX = __floats2bfloat162_rn(1.f, 1.f);
                avY = avX;
                base = 684;
            }
            mydX[0][l] = avX;
            mydY[0][l] = avY;
            __syncwarp();

            // depth-8 prefetch rings (both chains)
            float2 fX0 = pre0X[(base + 0) * 32], fX1 = pre0X[(base + 1) * 32];
            float2 fX2 = pre0X[(base + 2) * 32], fX3 = pre0X[(base + 3) * 32];
            float2 fX4 = pre0X[(base + 4) * 32], fX5 = pre0X[(base + 5) * 32];
            float2 fX6 = pre0X[(base + 6) * 32], fX7 = pre0X[(base + 7) * 32];
            float2 fY0 = pre0Y[(base + 0) * 32], fY1 = pre0Y[(base + 1) * 32];
            float2 fY2 = pre0Y[(base + 2) * 32], fY3 = pre0Y[(base + 3) * 32];
            float2 fY4 = pre0Y[(base + 4) * 32], fY5 = pre0Y[(base + 5) * 32];
            float2 fY6 = pre0Y[(base + 6) * 32], fY7 = pre0Y[(base + 7) * 32];
            const float2* preX = pre0X + (base + 8) * 32;
            const float2* preY = pre0Y + (base + 8) * 32;

            // 85 groups of 8 + 3 tail = 683 steps (prefetch <= base+690 <= 1374)
            #pragma unroll 1
            for (int grp = 0; grp < 85; grp++) {
                FS2(0, fX0, fY0); FS2(1, fX1, fY1); FS2(0, fX2, fY2); FS2(1, fX3, fY3);
                FS2(0, fX4, fY4); FS2(1, fX5, fY5); FS2(0, fX6, fY6); FS2_R(1, fX7, fY7);
            }
            FS2(0, fX0, fY0); FS2(1, fX1, fY1); FS2(0, fX2, fY2);

            rescale(avX, offX);   // final peg
            rescale(avY, offY);
            float* dX = (role == 0) ? g_vecA[b0] : g_vecF[b0];
            float* dY = (role == 0) ? g_vecA[b1] : g_vecF[b1];
            dX[2 * l] = __low2float(avX); dX[2 * l + 1] = __high2float(avX);
            dY[2 * l] = __low2float(avY); dY[2 * l + 1] = __high2float(avY);
            if (l == 0 && role == 0) { g_offA[b0] = offX; g_offA[b1] = offY; }
            // f's offset cancels in the final ratio
        } else {
            int base;
            if (role == 3) {
                float2 sk = ((const float2*)sink)[l];
                avX = __floats2bfloat162_rn(__expf(sk.x), __expf(sk.y));
                avY = avX;
                base = 2047;
            } else {
                avX = __floats2bfloat162_rn(1.f, 1.f);
                avY = avX;
                base = 1366;
            }

            float2 fX0 = pre0X[(base - 0) * 32], fX1 = pre0X[(base - 1) * 32];
            float2 fX2 = pre0X[(base - 2) * 32], fX3 = pre0X[(base - 3) * 32];
            float2 fX4 = pre0X[(base - 4) * 32], fX5 = pre0X[(base - 5) * 32];
            float2 fX6 = pre0X[(base - 6) * 32], fX7 = pre0X[(base - 7) * 32];
            float2 fY0 = pre0Y[(base - 0) * 32], fY1 = pre0Y[(base - 1) * 32];
            float2 fY2 = pre0Y[(base - 2) * 32], fY3 = pre0Y[(base - 3) * 32];
            float2 fY4 = pre0Y[(base - 4) * 32], fY5 = pre0Y[(base - 5) * 32];
            float2 fY6 = pre0Y[(base - 6) * 32], fY7 = pre0Y[(base - 7) * 32];
            const float2* preX = pre0X + (base - 8) * 32;
            const float2* preY = pre0Y + (base - 8) * 32;

            // role2: 85x8+3 = 683 steps (rows 1366..684);
            // role3: 85x8+1 = 681 steps (rows 2047..1367).
            // Prefetch >= base-690 >= 676, in bounds.
            #pragma unroll 1
            for (int grp = 0; grp < 85; grp++) {
                BS2(0, fX0, fY0); BS2(1, fX1, fY1); BS2(0, fX2, fY2); BS2(1, fX3, fY3);
                BS2(0, fX4, fY4); BS2(1, fX5, fY5); BS2(0, fX6, fY6); BS2_R(1, fX7, fY7);
            }
            BS2(0, fX0, fY0);
            if (role == 2) { BS2(1, fX1, fY1); BS2(0, fX2, fY2); }

            rescale(avX, offX);   // final peg
            rescale(avY, offY);
            float* dX = (role == 2) ? g_vecG[b0] : g_vecB[b0];
            float* dY = (role == 2) ? g_vecG[b1] : g_vecB[b1];
            dX[2 * l] = __low2float(avX); dX[2 * l + 1] = __high2float(avX);
            dY[2 * l] = __low2float(avY); dY[2 * l + 1] = __high2float(avY);
            if (l == 0) {
                if (role == 2) { g_offG[b0] = offX; g_offG[b1] = offY; }
                else           { g_offB[b0] = offX; g_offB[b1] = offY; }
            }
        }
    }

    // ---------------- completion: last block reduces ----------------
    __syncthreads();
    if (threadIdx.x == 0) {
        __threadfence();
        s_last = (atomicAdd(&g_done, 1u) == NBLK - 1u) ? 1 : 0;
    }
    __syncthreads();
    if (!s_last) return;
    __threadfence();

    // loss_b = log(A.g) + log(f.beta) - log(f.1) + offA + offG + offB - gold
    for (int b = threadIdx.x; b < NB; b += 128) {
        float dAG = 0.f, dFB = 0.f, dF1 = 0.f;
        #pragma unroll 4
        for (int j = 0; j < NK; j++) {
            float fj = g_vecF[b][j];
            dAG += g_vecA[b][j] * g_vecG[b][j];
            dFB += fj * g_vecB[b][j];
            dF1 += fj;
        }
        red[b] = logf(dAG) + logf(dFB) - logf(dF1)
               + g_offA[b] + g_offG[b] + g_offB[b] - g_gold[b];
    }
    __syncthreads();
    if (threadIdx.x < 32) {
        float s = 0.f;
        for (int i = threadIdx.x; i < NB; i += 32) s += red[i];
        #pragma unroll
        for (int d = 16; d; d >>= 1) s += __shfl_xor_sync(0xffffffffu, s, d);
        if (threadIdx.x == 0) { out[0] = s * (1.0f / NB); g_done = 0; }
    }
}

extern "C" void kernel_launch(void* const* d_in, const int* in_sizes, int n_in,
                              void* d_out, int out_size)
{
    const float* scores = (const float*)d_in[0];
    const int*   states = (const int*)d_in[1];
    const float* trans  = (const float*)d_in[2];
    const float* source = (const float*)d_in[3];
    const float* sink   = (const float*)d_in[4];

    crf_fused<<<NBLK, 128>>>(scores, states, trans, source, sink, (float*)d_out);
}

// round 13
// speedup vs baseline: 2.3718x; 2.3718x over previous
#include <cuda_runtime.h>
#include <cuda_bf16.h>
#include <cstdint>

#define NB 256
#define NS 2048
#define NK 64
#define LN2F 0.69314718055994531f
#define NBLK 148
#define WPB 8             // 8 warps per block (256 threads), 1 block/SM
#define NWCH 1024         // chain warps: 4 per batch (s=3 stitch)

// Scratch (device globals — no allocation allowed)
__device__ float g_vecA[NB][NK];   // alpha_683 (true fwd)
__device__ float g_vecF[NB][NK];   // f = 1^T M2
__device__ float g_vecG[NB][NK];   // g = M2 1
__device__ float g_vecB[NB][NK];   // beta_1366 (true bwd)
__device__ float g_offA[NB];
__device__ float g_offG[NB];
__device__ float g_offB[NB];
__device__ float g_gold[NB];
__device__ unsigned g_done;        // zero-init; reset by last block each launch

typedef __nv_bfloat162 bf2;

__device__ __forceinline__ bf2 u2b(unsigned u) { return *reinterpret_cast<bf2*>(&u); }
__device__ __forceinline__ unsigned b2u(bf2 v) { return *reinterpret_cast<unsigned*>(&v); }

// Compiler-only ordering fence: loop body is branch-free so the warp stays
// convergent; MIO executes shared ops in issue order; ptxas cannot prove the
// LDS/STS disjoint so it keeps program order. No WARPSYNC instruction.
#define CFENCE() asm volatile("" ::: "memory")

// matvec, plain-packed vector (lane i holds pair (a_2i, a_2i+1) as one bf2):
// 8x LDS.128 + 64x HFMA2; Ee/Eo = this lane's even/odd output column banks.
__device__ __forceinline__ void mv2(const bf2* __restrict__ s,
                                    const unsigned (&Ee)[32], const unsigned (&Eo)[32],
                                    float& zl, float& zh) {
    const uint4* q = (const uint4*)s;
    bf2 zz = __floats2bfloat162_rn(0.f, 0.f);
    bf2 ce0 = zz, ce1 = zz, co0 = zz, co1 = zz;
    #pragma unroll
    for (int g = 0; g < 8; g++) {
        uint4 v = q[g];
        ce0 = __hfma2(u2b(v.x), u2b(Ee[4 * g + 0]), ce0);
        co0 = __hfma2(u2b(v.x), u2b(Eo[4 * g + 0]), co0);
        ce1 = __hfma2(u2b(v.y), u2b(Ee[4 * g + 1]), ce1);
        co1 = __hfma2(u2b(v.y), u2b(Eo[4 * g + 1]), co1);
        ce0 = __hfma2(u2b(v.z), u2b(Ee[4 * g + 2]), ce0);
        co0 = __hfma2(u2b(v.z), u2b(Eo[4 * g + 2]), co0);
        ce1 = __hfma2(u2b(v.w), u2b(Ee[4 * g + 3]), ce1);
        co1 = __hfma2(u2b(v.w), u2b(Eo[4 * g + 3]), co1);
    }
    bf2 ce = __hadd2(ce0, ce1), co = __hadd2(co0, co1);
    zl = __low2float(ce) + __high2float(ce);
    zh = __low2float(co) + __high2float(co);
}

// Exact power-of-two rescale (warp max via 5 shfl), offset in log domain.
__device__ __forceinline__ void rescale(bf2& v, float& off) {
    bf2 m2 = v;
    #pragma unroll
    for (int d = 16; d; d >>= 1)
        m2 = __hmax2(m2, u2b(__shfl_xor_sync(0xffffffffu, b2u(m2), d)));
    float m = fmaxf(__low2float(m2), __high2float(m2));
    int k = (__float_as_int(m) >> 23) - 127;
    k = k < -120 ? -120 : (k > 120 ? 120 : k);
    float scl = __int_as_float((127 - k) << 23);   // 2^-k (exact in bf16)
    v = __hmul2(v, __floats2bfloat162_rn(scl, scl));
    off += (float)k * LN2F;
}

// ---- forward step: exp early -> matvec(read P) -> mul -> store P^1 ----
#define FSTEP(P, BUF) do {                                              \
    float2 sv_ = BUF; BUF = *pre; pre += 32;                            \
    float e0_ = __expf(sv_.x), e1_ = __expf(sv_.y);                     \
    float zl_, zh_; mv2(myd[P], Ee, Eo, zl_, zh_);                      \
    av = __floats2bfloat162_rn(zl_ * e0_, zh_ * e1_);                   \
    myd[P ^ 1][l] = av;                                                 \
    CFENCE();                                                           \
} while (0)

#define FSTEP_R(P, BUF) do {                                            \
    float2 sv_ = BUF; BUF = *pre; pre += 32;                            \
    float e0_ = __expf(sv_.x), e1_ = __expf(sv_.y);                     \
    float zl_, zh_; mv2(myd[P], Ee, Eo, zl_, zh_);                      \
    av = __floats2bfloat162_rn(zl_ * e0_, zh_ * e1_);                   \
    rescale(av, off);                                                   \
    myd[P ^ 1][l] = av;                                                 \
    CFENCE();                                                           \
} while (0)

// ---- backward step: exp early -> w = av*e -> store P -> matvec(read P) ----
#define BSTEP(P, BUF) do {                                              \
    float2 sv_ = BUF; BUF = *pre; pre -= 32;                            \
    bf2 e_ = __floats2bfloat162_rn(__expf(sv_.x), __expf(sv_.y));       \
    bf2 w_ = __hmul2(av, e_);                                           \
    myd[P][l] = w_;                                                     \
    CFENCE();                                                           \
    float zl_, zh_; mv2(myd[P], Ee, Eo, zl_, zh_);                      \
    av = __floats2bfloat162_rn(zl_, zh_);                               \
} while (0)

#define BSTEP_R(P, BUF) do {                                            \
    float2 sv_ = BUF; BUF = *pre; pre -= 32;                            \
    bf2 e_ = __floats2bfloat162_rn(__expf(sv_.x), __expf(sv_.y));       \
    bf2 w_ = __hmul2(av, e_);                                           \
    rescale(w_, off);                                                   \
    myd[P][l] = w_;                                                     \
    CFENCE();                                                           \
    float zl_, zh_; mv2(myd[P], Ee, Eo, zl_, zh_);                      \
    av = __floats2bfloat162_rn(zl_, zh_);                               \
} while (0)

// 148 blocks x 8 warps = 1184 warp slots, 1 block/SM.
//  gid in [0,1024): chain warps — batch = gid>>2, role = gid&3:
//    role0: A    (true fwd,  rows 1..683,     683 steps, seed source+s0, off)
//    role1: f    (fwd ones,  rows 684..1366,  683 steps, off cancels)
//    role2: g    (bwd ones,  rows 1366..684,  683 steps, off)
//    role3: beta (true bwd,  rows 2047..1367, 681 steps, seed sink, off)
//  gid in [1024,1184): gold-path warps (batches strided by 160).
// Last block to finish computes the final loss.
__global__ void __launch_bounds__(32 * WPB, 1)
crf_fused(const float* __restrict__ scores, const int* __restrict__ states,
          const float* __restrict__ trans, const float* __restrict__ source,
          const float* __restrict__ sink, float* __restrict__ out)
{
    __shared__ __align__(16) bf2 vbuf[WPB][2][32];   // [warp][buf][packed pair]
    __shared__ float red[NB];
    __shared__ int s_last;

    const int w = threadIdx.x >> 5;
    const int l = threadIdx.x & 31;
    const int gid = blockIdx.x * WPB + w;

    if (gid >= NWCH) {
        // ---------------- gold path (1-2 batches per warp) ----------------
        for (int b = gid - NWCH; b < NB; b += 160) {
            const int* st = states + b * NS;
            const float* sc = scores + (size_t)b * NS * NK;
            float acc = 0.f;
            #pragma unroll 4
            for (int t = l; t < NS; t += 32) {
                int s = st[t];
                float e = sc[t * NK + s];
                float tr = (t + 1 < NS) ? trans[s * NK + st[t + 1]] : 0.f;
                acc += e + tr;
            }
            #pragma unroll
            for (int d = 16; d; d >>= 1) acc += __shfl_xor_sync(0xffffffffu, acc, d);
            if (l == 0) g_gold[b] = acc + source[st[0]] + sink[st[NS - 1]];
        }
    } else {
        // ---------------- one segment-chain per warp ----------------
        const int b = gid >> 2;
        const int role = gid & 3;
        const bool fwd = role < 2;
        bf2 (*myd)[32] = vbuf[w];

        // E banks: lane's even output column (2l) in Ee, odd (2l+1) in Eo,
        // input index packed in pairs matching the vector layout.
        unsigned Ee[32], Eo[32];
        if (fwd) {
            // z[c] = sum_i a[i] E[i][c]
            #pragma unroll
            for (int i2 = 0; i2 < 32; i2++) {
                const float* r0 = trans + (2 * i2) * NK;
                const float* r1 = trans + (2 * i2 + 1) * NK;
                Ee[i2] = b2u(__floats2bfloat162_rn(__expf(r0[2 * l]),     __expf(r1[2 * l])));
                Eo[i2] = b2u(__floats2bfloat162_rn(__expf(r0[2 * l + 1]), __expf(r1[2 * l + 1])));
            }
        } else {
            // beta'[r] = sum_j E[r][j] w[j]; rows 2l (Ee) and 2l+1 (Eo).
            #pragma unroll
            for (int j2 = 0; j2 < 32; j2++) {
                float2 e0v = ((const float2*)(trans + (2 * l) * NK))[j2];
                float2 e1v = ((const float2*)(trans + (2 * l + 1) * NK))[j2];
                Ee[j2] = b2u(__floats2bfloat162_rn(__expf(e0v.x), __expf(e0v.y)));
                Eo[j2] = b2u(__floats2bfloat162_rn(__expf(e1v.x), __expf(e1v.y)));
            }
        }

        const float2* pre0 = (const float2*)(scores + (size_t)b * NS * NK) + l;
        float off = 0.f;
        bf2 av;

        if (fwd) {
            int base;   // first consumed score row
            if (role == 0) {
                // alpha_0 = exp(source + scores[b,0,:])
                float2 s0 = pre0[0];
                float2 sr = ((const float2*)source)[l];
                av = __floats2bfloat162_rn(__expf(sr.x + s0.x), __expf(sr.y + s0.y));
                base = 1;
            } else {
                av = __floats2bfloat162_rn(1.f, 1.f);
                base = 684;
            }
            myd[0][l] = av;
            __syncwarp();   // one-time init sync

            // depth-8 prefetch ring
            float2 f0 = pre0[(base + 0) * 32], f1 = pre0[(base + 1) * 32];
            float2 f2 = pre0[(base + 2) * 32], f3 = pre0[(base + 3) * 32];
            float2 f4 = pre0[(base + 4) * 32], f5 = pre0[(base + 5) * 32];
            float2 f6 = pre0[(base + 6) * 32], f7 = pre0[(base + 7) * 32];
            const float2* pre = pre0 + (base + 8) * 32;

            // 85 groups of 8 + 3 tail = 683 steps (prefetch <= base+690 <= 1374)
            #pragma unroll 1
            for (int grp = 0; grp < 85; grp++) {
                FSTEP(0, f0); FSTEP(1, f1); FSTEP(0, f2); FSTEP(1, f3);
                FSTEP(0, f4); FSTEP(1, f5); FSTEP(0, f6); FSTEP_R(1, f7);
            }
            FSTEP(0, f0); FSTEP(1, f1); FSTEP(0, f2);

            rescale(av, off);   // final peg
            float* dst = (role == 0) ? g_vecA[b] : g_vecF[b];
            dst[2 * l]     = __low2float(av);
            dst[2 * l + 1] = __high2float(av);
            if (l == 0 && role == 0) g_offA[b] = off;   // f's offset cancels
        } else {
            int base;   // first consumed score row (descending)
            if (role == 2) {
                av = __floats2bfloat162_rn(1.f, 1.f);
                base = 1366;
            } else {
                float2 sk = ((const float2*)sink)[l];
                av = __floats2bfloat162_rn(__expf(sk.x), __expf(sk.y));
                base = 2047;
            }

            // depth-8 prefetch ring (descending)
            float2 f0 = pre0[(base - 0) * 32], f1 = pre0[(base - 1) * 32];
            float2 f2 = pre0[(base - 2) * 32], f3 = pre0[(base - 3) * 32];
            float2 f4 = pre0[(base - 4) * 32], f5 = pre0[(base - 5) * 32];
            float2 f6 = pre0[(base - 6) * 32], f7 = pre0[(base - 7) * 32];
            const float2* pre = pre0 + (base - 8) * 32;

            // role2: 85x8+3 = 683 steps (rows 1366..684);
            // role3: 85x8+1 = 681 steps (rows 2047..1367).
            // Prefetch >= base-690 >= 676, in bounds.
            #pragma unroll 1
            for (int grp = 0; grp < 85; grp++) {
                BSTEP(0, f0); BSTEP(1, f1); BSTEP(0, f2); BSTEP(1, f3);
                BSTEP(0, f4); BSTEP(1, f5); BSTEP(0, f6); BSTEP_R(1, f7);
            }
            BSTEP(0, f0);
            if (role == 2) { BSTEP(1, f1); BSTEP(0, f2); }

            rescale(av, off);   // final peg
            float* dst = (role == 2) ? g_vecG[b] : g_vecB[b];
            dst[2 * l]     = __low2float(av);
            dst[2 * l + 1] = __high2float(av);
            if (l == 0) {
                if (role == 2) g_offG[b] = off; else g_offB[b] = off;
            }
        }
    }

    // ---------------- completion: last block reduces ----------------
    __syncthreads();
    if (threadIdx.x == 0) {
        __threadfence();
        s_last = (atomicAdd(&g_done, 1u) == NBLK - 1u) ? 1 : 0;
    }
    __syncthreads();
    if (!s_last) return;
    __threadfence();

    // loss_b = log(A.g) + log(f.beta) - log(f.1) + offA + offG + offB - gold
    if (threadIdx.x < NB) {
        const int b = threadIdx.x;
        float dAG = 0.f, dFB = 0.f, dF1 = 0.f;
        #pragma unroll 4
        for (int j = 0; j < NK; j++) {
            float fj = g_vecF[b][j];
            dAG += g_vecA[b][j] * g_vecG[b][j];
            dFB += fj * g_vecB[b][j];
            dF1 += fj;
        }
        red[b] = logf(dAG) + logf(dFB) - logf(dF1)
               + g_offA[b] + g_offG[b] + g_offB[b] - g_gold[b];
    }
    __syncthreads();
    if (threadIdx.x < 32) {
        float s = 0.f;
        for (int i = threadIdx.x; i < NB; i += 32) s += red[i];
        #pragma unroll
        for (int d = 16; d; d >>= 1) s += __shfl_xor_sync(0xffffffffu, s, d);
        if (threadIdx.x == 0) { out[0] = s * (1.0f / NB); g_done = 0; }
    }
}

extern "C" void kernel_launch(void* const* d_in, const int* in_sizes, int n_in,
                              void* d_out, int out_size)
{
    const float* scores = (const float*)d_in[0];
    const int*   states = (const int*)d_in[1];
    const float* trans  = (const float*)d_in[2];
    const float* source = (const float*)d_in[3];
    const float* sink   = (const float*)d_in[4];

    crf_fused<<<NBLK, 32 * WPB>>>(scores, states, trans, source, sink, (float*)d_out);
}